// round 5
// baseline (speedup 1.0000x reference)
#include <cuda_runtime.h>
#include <cuda_fp16.h>
#include <cstdint>

#define NN 50000
#define EE 800000
#define NBLK 49   // ceil(50000/1024)

// ---------------- scratch (device globals; zero-init at load) ---------------
__device__ __align__(16) __half2 g_xsh[NN * 64];  // transformed feats, half2
__device__ __align__(16) float g_h[NN * 128];
__device__ __align__(16) float4 g_edat[EE];       // (src, exp(a0), ae1, _) sorted
__device__ float g_als[NN];
__device__ float g_ald[NN];
__device__ int   g_deg[NN];      // self-cleaned in k_scan_apply
__device__ int   g_off[NN + 1];
__device__ int   g_cur[NN];
__device__ int   g_pos[EE];
__device__ int   g_bsum[64];
__device__ float g_bnacc[512];   // self-cleaned in agg finalizer
__device__ unsigned g_ctr[2];    // self-cleaned in agg finalizer
__device__ float g_scale[256];
__device__ float g_shift[256];
__device__ float g_ced[16];

// ---------------- f32x2 packed math (sm_100+) ------------------------------
#define FMA2(d, a, b, c) \
    asm("fma.rn.f32x2 %0, %1, %2, %3;" : "=l"(d) : "l"(a), "l"(b), "l"(c))
#define PACK2(d, lo, hi) \
    asm("mov.b64 %0, {%1, %2};" : "=l"(d) : "r"(lo), "r"(hi))
#define UNPACK2(lo, hi, s) \
    asm("mov.b64 {%0, %1}, %2;" : "=r"(lo), "=r"(hi) : "l"(s))

// ---------------- CSR build -------------------------------------------------
__global__ void k_hist(const int4* __restrict__ dst4) {
    int i = blockIdx.x * blockDim.x + threadIdx.x;
    if (i < EE / 4) {
        int4 d = dst4[i];
        atomicAdd(&g_deg[d.x], 1);
        atomicAdd(&g_deg[d.y], 1);
        atomicAdd(&g_deg[d.z], 1);
        atomicAdd(&g_deg[d.w], 1);
    }
}

__global__ __launch_bounds__(1024) void k_scan_part() {
    __shared__ int ws[32];
    const int tid = threadIdx.x, lane = tid & 31, wid = tid >> 5;
    int i = blockIdx.x * 1024 + tid;
    int v = (i < NN) ? g_deg[i] : 0;
    int x = v;
    #pragma unroll
    for (int o = 1; o < 32; o <<= 1) {
        int t = __shfl_up_sync(0xffffffffu, x, o);
        if (lane >= o) x += t;
    }
    if (lane == 31) ws[wid] = x;
    __syncthreads();
    if (wid == 0) {
        int y = ws[lane];
        #pragma unroll
        for (int o = 1; o < 32; o <<= 1) {
            int t = __shfl_up_sync(0xffffffffu, y, o);
            if (lane >= o) y += t;
        }
        ws[lane] = y;
    }
    __syncthreads();
    int excl = x - v + ((wid > 0) ? ws[wid - 1] : 0);
    if (i < NN) g_off[i] = excl;
    if (tid == 1023) g_bsum[blockIdx.x] = excl + v;
}

__global__ __launch_bounds__(1024) void k_scan_apply() {
    __shared__ int s_pre[2];
    const int tid = threadIdx.x, bid = blockIdx.x;
    if (tid < 64) {
        int v = (tid < bid) ? g_bsum[tid] : 0;
        #pragma unroll
        for (int o = 16; o; o >>= 1) v += __shfl_xor_sync(0xffffffffu, v, o);
        if ((tid & 31) == 0) s_pre[tid >> 5] = v;
    }
    __syncthreads();
    int bp = s_pre[0] + s_pre[1];
    int i = bid * 1024 + tid;
    if (i < NN) {
        int o = g_off[i] + bp;
        g_off[i] = o;
        g_cur[i] = o;
        g_deg[i] = 0;    // self-clean
    }
    if (bid == NBLK - 1 && tid == 1023) g_off[NN] = bp + g_bsum[NBLK - 1];
}

__global__ void k_scatter(const int* __restrict__ dst) {
    int e = blockIdx.x * blockDim.x + threadIdx.x;
    if (e >= EE) return;
    g_pos[e] = atomicAdd(&g_cur[dst[e]], 1);
}

// ---------------- ced for both layers ---------------------------------------
__global__ void k_ced(const float* __restrict__ We0, const float* __restrict__ ae0,
                      const float* __restrict__ We1, const float* __restrict__ ae1) {
    int j = threadIdx.x;
    if (j < 8) {
        float s = 0.f;
        for (int c = 0; c < 128; c++) s += We0[j * 128 + c] * ae0[c];
        g_ced[j] = s;
    } else if (j < 16) {
        int jj = j - 8;
        float s = 0.f;
        for (int c = 0; c < 112; c++) s += We1[jj * 112 + c] * ae1[c];
        g_ced[j] = s;
    }
}

// ---------------- GEMM -> half2 out (+optional BN-relu pre, +al epilogue) ---
template <int COUT, bool PRE>
__launch_bounds__(256)
__global__ void k_gemm(const float* __restrict__ A, const float* __restrict__ W,
                       const float* __restrict__ asrc, const float* __restrict__ adst,
                       __half2* __restrict__ Out) {
    __shared__ float As[128 * 33];
    __shared__ float Bs[32 * 128];
    const int tid = threadIdx.x;
    const int tx = tid & 15, ty = tid >> 4;
    const int row0 = blockIdx.x * 128;
    constexpr int TXMAX = COUT / 8;      // 16 or 14
    constexpr int H2S = COUT / 2;        // half2 row stride

    unsigned long long acc[8][4];
    #pragma unroll
    for (int r = 0; r < 8; r++)
        #pragma unroll
        for (int j = 0; j < 4; j++) acc[r][j] = 0ull;

    for (int k0 = 0; k0 < 128; k0 += 32) {
        #pragma unroll
        for (int t = 0; t < 4; t++) {
            int idx = tid + t * 256;
            int r = idx >> 3, c4 = (idx & 7) * 4;
            int gr = row0 + r;
            float4 v = make_float4(0.f, 0.f, 0.f, 0.f);
            if (gr < NN) {
                v = *(const float4*)(A + (size_t)gr * 128 + k0 + c4);
                if (PRE) {
                    int ch = k0 + c4;
                    v.x = fmaxf(fmaf(v.x, g_scale[ch + 0], g_shift[ch + 0]), 0.f);
                    v.y = fmaxf(fmaf(v.y, g_scale[ch + 1], g_shift[ch + 1]), 0.f);
                    v.z = fmaxf(fmaf(v.z, g_scale[ch + 2], g_shift[ch + 2]), 0.f);
                    v.w = fmaxf(fmaf(v.w, g_scale[ch + 3], g_shift[ch + 3]), 0.f);
                }
            }
            float* dp = &As[r * 33 + c4];
            dp[0] = v.x; dp[1] = v.y; dp[2] = v.z; dp[3] = v.w;
        }
        #pragma unroll
        for (int t = 0; t < 16; t++) {
            int idx = tid + t * 256;
            int kk = idx >> 7, c = idx & 127;
            Bs[idx] = (c < COUT) ? W[(size_t)(k0 + kk) * COUT + c] : 0.f;
        }
        __syncthreads();
        #pragma unroll
        for (int kk = 0; kk < 32; kk++) {
            float4 bl = *(const float4*)&Bs[kk * 128 + tx * 8];
            float4 bh = *(const float4*)&Bs[kk * 128 + tx * 8 + 4];
            unsigned long long b2[4];
            PACK2(b2[0], __float_as_uint(bl.x), __float_as_uint(bl.y));
            PACK2(b2[1], __float_as_uint(bl.z), __float_as_uint(bl.w));
            PACK2(b2[2], __float_as_uint(bh.x), __float_as_uint(bh.y));
            PACK2(b2[3], __float_as_uint(bh.z), __float_as_uint(bh.w));
            #pragma unroll
            for (int r = 0; r < 8; r++) {
                float a = As[(ty * 8 + r) * 33 + kk];
                unsigned long long a2;
                PACK2(a2, __float_as_uint(a), __float_as_uint(a));
                #pragma unroll
                for (int j = 0; j < 4; j++) FMA2(acc[r][j], a2, b2[j], acc[r][j]);
            }
        }
        __syncthreads();
    }
    // epilogue: half2 store + attention logits
    #pragma unroll
    for (int r = 0; r < 8; r++) {
        int gr = row0 + ty * 8 + r;
        float ps = 0.f, pd = 0.f;
        float vals[8];
        #pragma unroll
        for (int j = 0; j < 4; j++) {
            unsigned lo, hi;
            UNPACK2(lo, hi, acc[r][j]);
            vals[2 * j] = __uint_as_float(lo);
            vals[2 * j + 1] = __uint_as_float(hi);
        }
        if (gr < NN && tx < TXMAX) {
            int cb = tx * 8;
            #pragma unroll
            for (int k = 0; k < 8; k++) {
                ps += vals[k] * asrc[cb + k];
                pd += vals[k] * adst[cb + k];
            }
            __half2 h0 = __floats2half2_rn(vals[0], vals[1]);
            __half2 h1 = __floats2half2_rn(vals[2], vals[3]);
            __half2 h2 = __floats2half2_rn(vals[4], vals[5]);
            __half2 h3 = __floats2half2_rn(vals[6], vals[7]);
            uint4 pk;
            pk.x = *(unsigned*)&h0; pk.y = *(unsigned*)&h1;
            pk.z = *(unsigned*)&h2; pk.w = *(unsigned*)&h3;
            *(uint4*)(Out + (size_t)gr * H2S + tx * 4) = pk;
        }
        #pragma unroll
        for (int o = 1; o < 16; o <<= 1) {
            ps += __shfl_xor_sync(0xffffffffu, ps, o);
            pd += __shfl_xor_sync(0xffffffffu, pd, o);
        }
        if (tx == 0 && gr < NN) { g_als[gr] = ps; g_ald[gr] = pd; }
    }
}

// ---------------- fused per-edge logits: one eatt pass for BOTH layers ------
__global__ void k_alphaF(const float* __restrict__ eatt, const int* __restrict__ src,
                         const int* __restrict__ dst) {
    int e = blockIdx.x * blockDim.x + threadIdx.x;
    if (e >= EE) return;
    const float4* er = (const float4*)(eatt + (size_t)e * 8);
    float4 e0 = er[0], e1 = er[1];
    float ae0 = e0.x * g_ced[0] + e0.y * g_ced[1] + e0.z * g_ced[2] + e0.w * g_ced[3]
              + e1.x * g_ced[4] + e1.y * g_ced[5] + e1.z * g_ced[6] + e1.w * g_ced[7];
    float ae1 = e0.x * g_ced[8] + e0.y * g_ced[9] + e0.z * g_ced[10] + e0.w * g_ced[11]
              + e1.x * g_ced[12] + e1.y * g_ced[13] + e1.z * g_ced[14] + e1.w * g_ced[15];
    int s = src[e];
    float a = g_als[s] + g_ald[dst[e]] + ae0;
    a = (a > 0.f) ? a : 0.2f * a;
    g_edat[g_pos[e]] = make_float4(__int_as_float(s), __expf(a), ae1, 0.f);
}

// ------- warp-per-node single-pass agg + fused BN stat/finalize -------------
template <int C, bool ALPHA1>
__launch_bounds__(256)
__global__ void k_agg(const float* __restrict__ bias, float* __restrict__ out,
                      const float* __restrict__ bgam, const float* __restrict__ bbet,
                      int accoff, int scoff, int cidx) {
    __shared__ float s_sum[C];
    __shared__ float s_sq[C];
    __shared__ unsigned s_ticket;
    const int tid = threadIdx.x;
    for (int c = tid; c < C; c += 256) { s_sum[c] = 0.f; s_sq[c] = 0.f; }
    __syncthreads();

    int gw = (blockIdx.x * 256 + tid) >> 5;
    int lane = tid & 31;
    constexpr int NL = C / 8;      // active lanes: 16 or 14
    constexpr int H2S = C / 2;
    const bool act = lane < NL;

    if (gw < NN) {
        int beg = g_off[gw], end = g_off[gw + 1];
        float aldv = ALPHA1 ? g_ald[gw] : 0.f;

        float den = 0.f;
        float acc[8];
        #pragma unroll
        for (int k = 0; k < 8; k++) acc[k] = 0.f;

        int p = beg;
        for (; p + 2 <= end; p += 2) {
            float4 ed0 = g_edat[p];
            float4 ed1 = g_edat[p + 1];
            int s0 = __float_as_int(ed0.x), s1 = __float_as_int(ed1.x);
            float w0, w1;
            if (ALPHA1) {
                float a0 = g_als[s0] + aldv + ed0.z;
                float a1 = g_als[s1] + aldv + ed1.z;
                a0 = (a0 > 0.f) ? a0 : 0.2f * a0;
                a1 = (a1 > 0.f) ? a1 : 0.2f * a1;
                w0 = __expf(a0); w1 = __expf(a1);
            } else {
                w0 = ed0.y; w1 = ed1.y;
            }
            den += w0 + w1;
            if (act) {
                uint4 r0 = *(const uint4*)(g_xsh + (size_t)s0 * H2S + lane * 4);
                uint4 r1 = *(const uint4*)(g_xsh + (size_t)s1 * H2S + lane * 4);
                const __half2* h0 = (const __half2*)&r0;
                const __half2* h1 = (const __half2*)&r1;
                #pragma unroll
                for (int k = 0; k < 4; k++) {
                    float2 f0 = __half22float2(h0[k]);
                    float2 f1 = __half22float2(h1[k]);
                    acc[2 * k + 0] += w0 * f0.x + w1 * f1.x;
                    acc[2 * k + 1] += w0 * f0.y + w1 * f1.y;
                }
            }
        }
        if (p < end) {
            float4 ed0 = g_edat[p];
            int s0 = __float_as_int(ed0.x);
            float w0;
            if (ALPHA1) {
                float a0 = g_als[s0] + aldv + ed0.z;
                a0 = (a0 > 0.f) ? a0 : 0.2f * a0;
                w0 = __expf(a0);
            } else {
                w0 = ed0.y;
            }
            den += w0;
            if (act) {
                uint4 r0 = *(const uint4*)(g_xsh + (size_t)s0 * H2S + lane * 4);
                const __half2* h0 = (const __half2*)&r0;
                #pragma unroll
                for (int k = 0; k < 4; k++) {
                    float2 f0 = __half22float2(h0[k]);
                    acc[2 * k + 0] += w0 * f0.x;
                    acc[2 * k + 1] += w0 * f0.y;
                }
            }
        }
        float inv = (end > beg) ? 1.f / den : 0.f;
        if (act) {
            int cb = lane * 8;
            #pragma unroll
            for (int k = 0; k < 8; k++) {
                acc[k] = fmaf(acc[k], inv, bias[cb + k]);
                atomicAdd(&s_sum[cb + k], acc[k]);
                atomicAdd(&s_sq[cb + k], acc[k] * acc[k]);
            }
            float4 o0 = make_float4(acc[0], acc[1], acc[2], acc[3]);
            float4 o1 = make_float4(acc[4], acc[5], acc[6], acc[7]);
            *(float4*)(out + (size_t)gw * C + cb) = o0;
            *(float4*)(out + (size_t)gw * C + cb + 4) = o1;
        }
    }
    __syncthreads();
    for (int c = tid; c < C; c += 256) {
        atomicAdd(&g_bnacc[accoff + c], s_sum[c]);
        atomicAdd(&g_bnacc[accoff + 128 + c], s_sq[c]);
    }
    // last-block BN finalize
    __threadfence();
    __syncthreads();
    if (tid == 0) s_ticket = atomicAdd(&g_ctr[cidx], 1u);
    __syncthreads();
    if (s_ticket == gridDim.x - 1) {
        __threadfence();
        if (tid < C) {
            float sum = __ldcg(&g_bnacc[accoff + tid]);
            float sq  = __ldcg(&g_bnacc[accoff + 128 + tid]);
            float mean = sum * (1.f / NN);
            float var = sq * (1.f / NN) - mean * mean;
            float sc = bgam[tid] * rsqrtf(var + 1e-5f);
            g_scale[scoff + tid] = sc;
            g_shift[scoff + tid] = bbet[tid] - mean * sc;
            g_bnacc[accoff + tid] = 0.f;
            g_bnacc[accoff + 128 + tid] = 0.f;
        }
        if (tid == 0) g_ctr[cidx] = 0u;
    }
}

// ---------------- final BN apply ---------------------------------------------
__global__ void k_out(const float* __restrict__ h, float* __restrict__ out) {
    int idx = blockIdx.x * blockDim.x + threadIdx.x;
    int i4 = idx * 4;
    if (i4 < NN * 112) {
        int c = i4 % 112;
        float4 v = *(const float4*)(h + i4);
        v.x = fmaf(v.x, g_scale[128 + c + 0], g_shift[128 + c + 0]);
        v.y = fmaf(v.y, g_scale[128 + c + 1], g_shift[128 + c + 1]);
        v.z = fmaf(v.z, g_scale[128 + c + 2], g_shift[128 + c + 2]);
        v.w = fmaf(v.w, g_scale[128 + c + 3], g_shift[128 + c + 3]);
        *(float4*)(out + i4) = v;
    }
}

// ---------------- launch -----------------------------------------------------
extern "C" void kernel_launch(void* const* d_in, const int* in_sizes, int n_in,
                              void* d_out, int out_size) {
    const float* x    = (const float*)d_in[0];
    const int*   ei   = (const int*)d_in[1];
    const float* eatt = (const float*)d_in[2];
    const float* W0   = (const float*)d_in[3];
    const float* as0  = (const float*)d_in[4];
    const float* ad0  = (const float*)d_in[5];
    const float* We0  = (const float*)d_in[6];
    const float* ae0  = (const float*)d_in[7];
    const float* b0   = (const float*)d_in[8];
    const float* W1   = (const float*)d_in[9];
    const float* as1  = (const float*)d_in[10];
    const float* ad1  = (const float*)d_in[11];
    const float* We1  = (const float*)d_in[12];
    const float* ae1  = (const float*)d_in[13];
    const float* b1   = (const float*)d_in[14];
    const float* bng  = (const float*)d_in[15];
    const float* bnb  = (const float*)d_in[16];
    const float* bfg  = (const float*)d_in[17];
    const float* bfb  = (const float*)d_in[18];
    float* out = (float*)d_out;

    const int* src = ei;
    const int* dst = ei + EE;

    __half2* p_xsh = nullptr;
    float* p_h = nullptr;
    cudaGetSymbolAddress((void**)&p_xsh, g_xsh);
    cudaGetSymbolAddress((void**)&p_h, g_h);

    static cudaStream_t s1 = nullptr;
    static cudaEvent_t evFork = nullptr, evJoin = nullptr;
    if (!s1) {
        cudaStreamCreateWithFlags(&s1, cudaStreamNonBlocking);
        cudaEventCreateWithFlags(&evFork, cudaEventDisableTiming);
        cudaEventCreateWithFlags(&evJoin, cudaEventDisableTiming);
    }

    const int TB = 256;
    const int gE = (EE + TB - 1) / TB;
    const int gE4 = (EE / 4 + TB - 1) / TB;
    const int gW = (NN * 32 + TB - 1) / TB;
    const int gG = (NN + 127) / 128;

    // ---- fork: ced + CSR build on s1, concurrent with gemm0 on main stream
    cudaEventRecord(evFork, 0);
    cudaStreamWaitEvent(s1, evFork, 0);

    k_ced<<<1, 32, 0, s1>>>(We0, ae0, We1, ae1);
    k_hist<<<gE4, TB, 0, s1>>>((const int4*)dst);
    k_scan_part<<<NBLK, 1024, 0, s1>>>();
    k_scan_apply<<<NBLK, 1024, 0, s1>>>();
    k_scatter<<<gE, TB, 0, s1>>>(dst);
    cudaEventRecord(evJoin, s1);

    k_gemm<128, false><<<gG, 256>>>(x, W0, as0, ad0, p_xsh);

    cudaStreamWaitEvent(0, evJoin, 0);

    // ---- layer 0
    k_alphaF<<<gE, TB>>>(eatt, src, dst);
    k_agg<128, false><<<gW, TB>>>(b0, p_h, bng, bnb, 0, 0, 0);

    // ---- layer 1 (BN+relu fused into A-load; alpha inline; BN fused)
    k_gemm<112, true><<<gG, 256>>>(p_h, W1, as1, ad1, p_xsh);
    k_agg<112, true><<<gW, TB>>>(b1, p_h, bfg, bfb, 256, 128, 1);
    k_out<<<(NN * 112 / 4 + TB - 1) / TB, TB>>>(p_h, out);
}

// round 6
// speedup vs baseline: 1.1256x; 1.1256x over previous
#include <cuda_runtime.h>
#include <cstdint>

#define NN 50000
#define EE 800000
#define NBLK 49   // ceil(50000/1024)

// ---------------- scratch (device globals; zero-init at load) ---------------
__device__ __align__(16) float g_xs[NN * 128];
__device__ __align__(16) float g_h[NN * 128];
__device__ __align__(8) float2 g_aes[EE];  // (ae0, ae1) sorted order
__device__ float g_als[NN];
__device__ float g_ald[NN];
__device__ int   g_deg[NN];      // self-cleaned in k_scan_apply
__device__ int   g_off[NN + 1];
__device__ int   g_cur[NN];
__device__ int   g_ssrc[EE];
__device__ int   g_pos[EE];
__device__ int   g_bsum[64];
__device__ float g_bnacc[512];   // self-cleaned in agg finalizer
__device__ unsigned g_ctr[2];    // self-cleaned in agg finalizer
__device__ float g_scale[256];
__device__ float g_shift[256];
__device__ float g_ced[16];

// ---------------- f32x2 packed math (sm_100+) ------------------------------
#define FMA2(d, a, b, c) \
    asm("fma.rn.f32x2 %0, %1, %2, %3;" : "=l"(d) : "l"(a), "l"(b), "l"(c))
#define PACK2(d, lo, hi) \
    asm("mov.b64 %0, {%1, %2};" : "=l"(d) : "r"(lo), "r"(hi))
#define UNPACK2(lo, hi, s) \
    asm("mov.b64 {%0, %1}, %2;" : "=r"(lo), "=r"(hi) : "l"(s))

// ---------------- CSR build -------------------------------------------------
__global__ void k_hist(const int4* __restrict__ dst4) {
    int i = blockIdx.x * blockDim.x + threadIdx.x;
    if (i < EE / 4) {
        int4 d = dst4[i];
        atomicAdd(&g_deg[d.x], 1);
        atomicAdd(&g_deg[d.y], 1);
        atomicAdd(&g_deg[d.z], 1);
        atomicAdd(&g_deg[d.w], 1);
    }
}

__global__ __launch_bounds__(1024) void k_scan_part() {
    __shared__ int ws[32];
    const int tid = threadIdx.x, lane = tid & 31, wid = tid >> 5;
    int i = blockIdx.x * 1024 + tid;
    int v = (i < NN) ? g_deg[i] : 0;
    int x = v;
    #pragma unroll
    for (int o = 1; o < 32; o <<= 1) {
        int t = __shfl_up_sync(0xffffffffu, x, o);
        if (lane >= o) x += t;
    }
    if (lane == 31) ws[wid] = x;
    __syncthreads();
    if (wid == 0) {
        int y = ws[lane];
        #pragma unroll
        for (int o = 1; o < 32; o <<= 1) {
            int t = __shfl_up_sync(0xffffffffu, y, o);
            if (lane >= o) y += t;
        }
        ws[lane] = y;
    }
    __syncthreads();
    int excl = x - v + ((wid > 0) ? ws[wid - 1] : 0);
    if (i < NN) g_off[i] = excl;
    if (tid == 1023) g_bsum[blockIdx.x] = excl + v;
}

__global__ __launch_bounds__(1024) void k_scan_apply() {
    __shared__ int s_pre[2];
    const int tid = threadIdx.x, bid = blockIdx.x;
    if (tid < 64) {
        int v = (tid < bid) ? g_bsum[tid] : 0;
        #pragma unroll
        for (int o = 16; o; o >>= 1) v += __shfl_xor_sync(0xffffffffu, v, o);
        if ((tid & 31) == 0) s_pre[tid >> 5] = v;
    }
    __syncthreads();
    int bp = s_pre[0] + s_pre[1];
    int i = bid * 1024 + tid;
    if (i < NN) {
        int o = g_off[i] + bp;
        g_off[i] = o;
        g_cur[i] = o;
        g_deg[i] = 0;    // self-clean
    }
    if (bid == NBLK - 1 && tid == 1023) g_off[NN] = bp + g_bsum[NBLK - 1];
}

__global__ void k_scatter(const int4* __restrict__ src4, const int4* __restrict__ dst4) {
    int i = blockIdx.x * blockDim.x + threadIdx.x;
    if (i >= EE / 4) return;
    int4 d = dst4[i];
    int4 s = src4[i];
    int4 p;
    p.x = atomicAdd(&g_cur[d.x], 1); g_ssrc[p.x] = s.x;
    p.y = atomicAdd(&g_cur[d.y], 1); g_ssrc[p.y] = s.y;
    p.z = atomicAdd(&g_cur[d.z], 1); g_ssrc[p.z] = s.z;
    p.w = atomicAdd(&g_cur[d.w], 1); g_ssrc[p.w] = s.w;
    *(int4*)&g_pos[i * 4] = p;
}

// ---------------- ced for both layers ---------------------------------------
__global__ void k_ced(const float* __restrict__ We0, const float* __restrict__ ae0,
                      const float* __restrict__ We1, const float* __restrict__ ae1) {
    int j = threadIdx.x;
    if (j < 8) {
        float s = 0.f;
        for (int c = 0; c < 128; c++) s += We0[j * 128 + c] * ae0[c];
        g_ced[j] = s;
    } else if (j < 16) {
        int jj = j - 8;
        float s = 0.f;
        for (int c = 0; c < 112; c++) s += We1[jj * 112 + c] * ae1[c];
        g_ced[j] = s;
    }
}

// ------- per-edge edge-attention terms, on fork stream (no als/ald needed) --
__global__ void k_aeF(const float* __restrict__ eatt) {
    int e = blockIdx.x * blockDim.x + threadIdx.x;
    if (e >= EE) return;
    const float4* er = (const float4*)(eatt + (size_t)e * 8);
    float4 e0 = er[0], e1 = er[1];
    float ae0 = e0.x * g_ced[0] + e0.y * g_ced[1] + e0.z * g_ced[2] + e0.w * g_ced[3]
              + e1.x * g_ced[4] + e1.y * g_ced[5] + e1.z * g_ced[6] + e1.w * g_ced[7];
    float ae1 = e0.x * g_ced[8] + e0.y * g_ced[9] + e0.z * g_ced[10] + e0.w * g_ced[11]
              + e1.x * g_ced[12] + e1.y * g_ced[13] + e1.z * g_ced[14] + e1.w * g_ced[15];
    g_aes[g_pos[e]] = make_float2(ae0, ae1);
}

// ---- GEMM, reg-double-buffered (+optional BN-relu pre, +al epilogue) -------
template <int COUT, bool PRE>
__launch_bounds__(256)
__global__ void k_gemm(const float* __restrict__ A, const float* __restrict__ W,
                       const float* __restrict__ asrc, const float* __restrict__ adst,
                       float* __restrict__ Out) {
    __shared__ float As[128 * 33];
    __shared__ float Bs[32 * 128];
    const int tid = threadIdx.x;
    const int tx = tid & 15, ty = tid >> 4;
    const int row0 = blockIdx.x * 128;

    unsigned long long acc[8][4];
    #pragma unroll
    for (int r = 0; r < 8; r++)
        #pragma unroll
        for (int j = 0; j < 4; j++) acc[r][j] = 0ull;

    float4 aReg[4];
    float bReg[16];

    // A-load addressing (constant across chunks)
    const int la_r = tid >> 3, la_c4 = (tid & 7) * 4;   // within the t-strided scheme below

    auto loadA = [&](int k0) {
        #pragma unroll
        for (int t = 0; t < 4; t++) {
            int idx = tid + t * 256;
            int r = idx >> 3, c4 = (idx & 7) * 4;
            int gr = row0 + r;
            float4 v = make_float4(0.f, 0.f, 0.f, 0.f);
            if (gr < NN) {
                v = *(const float4*)(A + (size_t)gr * 128 + k0 + c4);
                if (PRE) {
                    int ch = k0 + c4;
                    v.x = fmaxf(fmaf(v.x, g_scale[ch + 0], g_shift[ch + 0]), 0.f);
                    v.y = fmaxf(fmaf(v.y, g_scale[ch + 1], g_shift[ch + 1]), 0.f);
                    v.z = fmaxf(fmaf(v.z, g_scale[ch + 2], g_shift[ch + 2]), 0.f);
                    v.w = fmaxf(fmaf(v.w, g_scale[ch + 3], g_shift[ch + 3]), 0.f);
                }
            }
            aReg[t] = v;
        }
    };
    auto loadB = [&](int k0) {
        #pragma unroll
        for (int t = 0; t < 16; t++) {
            int idx = tid + t * 256;
            int kk = idx >> 7, c = idx & 127;
            bReg[t] = (c < COUT) ? W[(size_t)(k0 + kk) * COUT + c] : 0.f;
        }
    };

    loadA(0);
    loadB(0);

    for (int k0 = 0; k0 < 128; k0 += 32) {
        // commit prefetched chunk to smem
        #pragma unroll
        for (int t = 0; t < 4; t++) {
            int idx = tid + t * 256;
            int r = idx >> 3, c4 = (idx & 7) * 4;
            float* dp = &As[r * 33 + c4];
            dp[0] = aReg[t].x; dp[1] = aReg[t].y; dp[2] = aReg[t].z; dp[3] = aReg[t].w;
        }
        #pragma unroll
        for (int t = 0; t < 16; t++) Bs[tid + t * 256] = bReg[t];
        __syncthreads();

        // prefetch next chunk (overlaps with compute below)
        if (k0 + 32 < 128) {
            loadA(k0 + 32);
            loadB(k0 + 32);
        }

        #pragma unroll
        for (int kk = 0; kk < 32; kk++) {
            float a[8], b[8];
            #pragma unroll
            for (int r = 0; r < 8; r++) a[r] = As[(ty * 8 + r) * 33 + kk];
            #pragma unroll
            for (int j = 0; j < 8; j++) b[j] = Bs[kk * 128 + tx + 16 * j];
            unsigned long long b2[4];
            #pragma unroll
            for (int j = 0; j < 4; j++)
                PACK2(b2[j], __float_as_uint(b[2 * j]), __float_as_uint(b[2 * j + 1]));
            #pragma unroll
            for (int r = 0; r < 8; r++) {
                unsigned long long a2;
                PACK2(a2, __float_as_uint(a[r]), __float_as_uint(a[r]));
                #pragma unroll
                for (int j = 0; j < 4; j++) FMA2(acc[r][j], a2, b2[j], acc[r][j]);
            }
        }
        __syncthreads();
    }
    (void)la_r; (void)la_c4;
    // epilogue: store + attention logits
    #pragma unroll
    for (int r = 0; r < 8; r++) {
        int gr = row0 + ty * 8 + r;
        float ps = 0.f, pd = 0.f;
        #pragma unroll
        for (int j = 0; j < 4; j++) {
            unsigned lo, hi;
            UNPACK2(lo, hi, acc[r][j]);
            float v0 = __uint_as_float(lo), v1 = __uint_as_float(hi);
            int c0 = tx + 16 * (2 * j), c1 = tx + 16 * (2 * j + 1);
            if (gr < NN) {
                if (c0 < COUT) {
                    Out[(size_t)gr * COUT + c0] = v0;
                    ps += v0 * asrc[c0];
                    pd += v0 * adst[c0];
                }
                if (c1 < COUT) {
                    Out[(size_t)gr * COUT + c1] = v1;
                    ps += v1 * asrc[c1];
                    pd += v1 * adst[c1];
                }
            }
        }
        #pragma unroll
        for (int o = 1; o < 16; o <<= 1) {
            ps += __shfl_xor_sync(0xffffffffu, ps, o);
            pd += __shfl_xor_sync(0xffffffffu, pd, o);
        }
        if (tx == 0 && gr < NN) { g_als[gr] = ps; g_ald[gr] = pd; }
    }
}

// ------- warp-per-node single-pass agg (inline logits) + fused BN -----------
template <int C, int AEC>
__launch_bounds__(256)
__global__ void k_agg(const float* __restrict__ bias, float* __restrict__ out,
                      const float* __restrict__ bgam, const float* __restrict__ bbet,
                      int accoff, int scoff, int cidx) {
    __shared__ float s_sum[C];
    __shared__ float s_sq[C];
    __shared__ unsigned s_ticket;
    const int tid = threadIdx.x;
    for (int c = tid; c < C; c += 256) { s_sum[c] = 0.f; s_sq[c] = 0.f; }
    __syncthreads();

    int gw = (blockIdx.x * 256 + tid) >> 5;
    int lane = tid & 31;
    constexpr int NV = C / 4;
    const bool act = lane < NV;

    if (gw < NN) {
        int beg = g_off[gw], end = g_off[gw + 1];
        float aldv = g_ald[gw];

        float den = 0.f;
        float4 acc = make_float4(0.f, 0.f, 0.f, 0.f);
        int p = beg;
        for (; p + 4 <= end; p += 4) {
            int s0 = g_ssrc[p], s1 = g_ssrc[p + 1];
            int s2 = g_ssrc[p + 2], s3 = g_ssrc[p + 3];
            float2 q0 = g_aes[p], q1 = g_aes[p + 1];
            float2 q2 = g_aes[p + 2], q3 = g_aes[p + 3];
            float a0 = g_als[s0] + aldv + (AEC ? q0.y : q0.x);
            float a1 = g_als[s1] + aldv + (AEC ? q1.y : q1.x);
            float a2 = g_als[s2] + aldv + (AEC ? q2.y : q2.x);
            float a3 = g_als[s3] + aldv + (AEC ? q3.y : q3.x);
            a0 = (a0 > 0.f) ? a0 : 0.2f * a0;
            a1 = (a1 > 0.f) ? a1 : 0.2f * a1;
            a2 = (a2 > 0.f) ? a2 : 0.2f * a2;
            a3 = (a3 > 0.f) ? a3 : 0.2f * a3;
            float w0 = __expf(a0), w1 = __expf(a1);
            float w2 = __expf(a2), w3 = __expf(a3);
            den += (w0 + w1) + (w2 + w3);
            if (act) {
                float4 v0 = *(const float4*)(g_xs + (size_t)s0 * C + lane * 4);
                float4 v1 = *(const float4*)(g_xs + (size_t)s1 * C + lane * 4);
                float4 v2 = *(const float4*)(g_xs + (size_t)s2 * C + lane * 4);
                float4 v3 = *(const float4*)(g_xs + (size_t)s3 * C + lane * 4);
                acc.x += (w0 * v0.x + w1 * v1.x) + (w2 * v2.x + w3 * v3.x);
                acc.y += (w0 * v0.y + w1 * v1.y) + (w2 * v2.y + w3 * v3.y);
                acc.z += (w0 * v0.z + w1 * v1.z) + (w2 * v2.z + w3 * v3.z);
                acc.w += (w0 * v0.w + w1 * v1.w) + (w2 * v2.w + w3 * v3.w);
            }
        }
        for (; p < end; p++) {
            int s0 = g_ssrc[p];
            float2 q0 = g_aes[p];
            float a0 = g_als[s0] + aldv + (AEC ? q0.y : q0.x);
            a0 = (a0 > 0.f) ? a0 : 0.2f * a0;
            float w0 = __expf(a0);
            den += w0;
            if (act) {
                float4 v0 = *(const float4*)(g_xs + (size_t)s0 * C + lane * 4);
                acc.x += w0 * v0.x; acc.y += w0 * v0.y;
                acc.z += w0 * v0.z; acc.w += w0 * v0.w;
            }
        }
        float inv = (end > beg) ? 1.f / den : 0.f;
        if (act) {
            float4 b = *(const float4*)(bias + lane * 4);
            acc.x = fmaf(acc.x, inv, b.x);
            acc.y = fmaf(acc.y, inv, b.y);
            acc.z = fmaf(acc.z, inv, b.z);
            acc.w = fmaf(acc.w, inv, b.w);
            *(float4*)(out + (size_t)gw * C + lane * 4) = acc;
            int c = lane * 4;
            atomicAdd(&s_sum[c + 0], acc.x); atomicAdd(&s_sq[c + 0], acc.x * acc.x);
            atomicAdd(&s_sum[c + 1], acc.y); atomicAdd(&s_sq[c + 1], acc.y * acc.y);
            atomicAdd(&s_sum[c + 2], acc.z); atomicAdd(&s_sq[c + 2], acc.z * acc.z);
            atomicAdd(&s_sum[c + 3], acc.w); atomicAdd(&s_sq[c + 3], acc.w * acc.w);
        }
    }
    __syncthreads();
    for (int c = tid; c < C; c += 256) {
        atomicAdd(&g_bnacc[accoff + c], s_sum[c]);
        atomicAdd(&g_bnacc[accoff + 128 + c], s_sq[c]);
    }
    // last-block BN finalize
    __threadfence();
    __syncthreads();
    if (tid == 0) s_ticket = atomicAdd(&g_ctr[cidx], 1u);
    __syncthreads();
    if (s_ticket == gridDim.x - 1) {
        __threadfence();
        if (tid < C) {
            float sum = __ldcg(&g_bnacc[accoff + tid]);
            float sq  = __ldcg(&g_bnacc[accoff + 128 + tid]);
            float mean = sum * (1.f / NN);
            float var = sq * (1.f / NN) - mean * mean;
            float sc = bgam[tid] * rsqrtf(var + 1e-5f);
            g_scale[scoff + tid] = sc;
            g_shift[scoff + tid] = bbet[tid] - mean * sc;
            g_bnacc[accoff + tid] = 0.f;
            g_bnacc[accoff + 128 + tid] = 0.f;
        }
        if (tid == 0) g_ctr[cidx] = 0u;
    }
}

// ---------------- final BN apply ---------------------------------------------
__global__ void k_out(const float* __restrict__ h, float* __restrict__ out) {
    int idx = blockIdx.x * blockDim.x + threadIdx.x;
    int i4 = idx * 4;
    if (i4 < NN * 112) {
        int c = i4 % 112;
        float4 v = *(const float4*)(h + i4);
        v.x = fmaf(v.x, g_scale[128 + c + 0], g_shift[128 + c + 0]);
        v.y = fmaf(v.y, g_scale[128 + c + 1], g_shift[128 + c + 1]);
        v.z = fmaf(v.z, g_scale[128 + c + 2], g_shift[128 + c + 2]);
        v.w = fmaf(v.w, g_scale[128 + c + 3], g_shift[128 + c + 3]);
        *(float4*)(out + i4) = v;
    }
}

// ---------------- launch -----------------------------------------------------
extern "C" void kernel_launch(void* const* d_in, const int* in_sizes, int n_in,
                              void* d_out, int out_size) {
    const float* x    = (const float*)d_in[0];
    const int*   ei   = (const int*)d_in[1];
    const float* eatt = (const float*)d_in[2];
    const float* W0   = (const float*)d_in[3];
    const float* as0  = (const float*)d_in[4];
    const float* ad0  = (const float*)d_in[5];
    const float* We0  = (const float*)d_in[6];
    const float* ae0  = (const float*)d_in[7];
    const float* b0   = (const float*)d_in[8];
    const float* W1   = (const float*)d_in[9];
    const float* as1  = (const float*)d_in[10];
    const float* ad1  = (const float*)d_in[11];
    const float* We1  = (const float*)d_in[12];
    const float* ae1  = (const float*)d_in[13];
    const float* b1   = (const float*)d_in[14];
    const float* bng  = (const float*)d_in[15];
    const float* bnb  = (const float*)d_in[16];
    const float* bfg  = (const float*)d_in[17];
    const float* bfb  = (const float*)d_in[18];
    float* out = (float*)d_out;

    const int* src = ei;
    const int* dst = ei + EE;

    float* p_xs = nullptr;
    float* p_h  = nullptr;
    cudaGetSymbolAddress((void**)&p_xs, g_xs);
    cudaGetSymbolAddress((void**)&p_h,  g_h);

    static cudaStream_t s1 = nullptr;
    static cudaEvent_t evFork = nullptr, evJoin = nullptr;
    if (!s1) {
        cudaStreamCreateWithFlags(&s1, cudaStreamNonBlocking);
        cudaEventCreateWithFlags(&evFork, cudaEventDisableTiming);
        cudaEventCreateWithFlags(&evJoin, cudaEventDisableTiming);
    }

    const int TB = 256;
    const int gE = (EE + TB - 1) / TB;
    const int gE4 = (EE / 4 + TB - 1) / TB;
    const int gW = (NN * 32 + TB - 1) / TB;
    const int gG = (NN + 127) / 128;

    // ---- fork: ced + CSR build + edge-attention terms on s1, || gemm0
    cudaEventRecord(evFork, 0);
    cudaStreamWaitEvent(s1, evFork, 0);

    k_ced<<<1, 32, 0, s1>>>(We0, ae0, We1, ae1);
    k_hist<<<gE4, TB, 0, s1>>>((const int4*)dst);
    k_scan_part<<<NBLK, 1024, 0, s1>>>();
    k_scan_apply<<<NBLK, 1024, 0, s1>>>();
    k_scatter<<<gE4, TB, 0, s1>>>((const int4*)src, (const int4*)dst);
    k_aeF<<<gE, TB, 0, s1>>>(eatt);
    cudaEventRecord(evJoin, s1);

    k_gemm<128, false><<<gG, 256>>>(x, W0, as0, ad0, p_xs);

    cudaStreamWaitEvent(0, evJoin, 0);

    // ---- layer 0 (alpha inline, BN finalize fused)
    k_agg<128, 0><<<gW, TB>>>(b0, p_h, bng, bnb, 0, 0, 0);

    // ---- layer 1 (BN+relu fused into A-load; alpha inline; BN fused)
    k_gemm<112, true><<<gG, 256>>>(p_h, W1, as1, ad1, p_xs);
    k_agg<112, 1><<<gW, TB>>>(b1, p_h, bfg, bfb, 256, 128, 1);
    k_out<<<(NN * 112 / 4 + TB - 1) / TB, TB>>>(p_h, out);
}

// round 7
// speedup vs baseline: 1.3583x; 1.2068x over previous
#include <cuda_runtime.h>
#include <cstdint>

#define NN 50000
#define EE 800000
#define NBLK 49   // ceil(50000/1024)

// ---------------- scratch (device globals; zero-init at load) ---------------
__device__ __align__(16) float g_xs[NN * 128];
__device__ __align__(16) float g_h[NN * 128];
__device__ __align__(8) float2 g_aes[EE];  // (ae0, ae1) sorted order
__device__ float g_als[NN];
__device__ float g_ald[NN];
__device__ int   g_deg[NN];      // self-cleaned in k_scan_apply
__device__ int   g_off[NN + 1];
__device__ int   g_cur[NN];
__device__ int   g_ssrc[EE];
__device__ int   g_bsum[64];
__device__ float g_bnacc[512];   // self-cleaned in agg finalizer
__device__ unsigned g_ctr[2];    // self-cleaned in agg finalizer
__device__ float g_scale[256];
__device__ float g_shift[256];
__device__ float g_ced[16];

// ---------------- tf32 helpers ----------------------------------------------
__device__ __forceinline__ float f2tf(float f) {
    unsigned u;
    asm("cvt.rna.tf32.f32 %0, %1;" : "=r"(u) : "f"(f));
    return __uint_as_float(u);
}

#define MMA_TF32(C, A, B) \
    asm volatile( \
        "mma.sync.aligned.m16n8k8.row.col.f32.tf32.tf32.f32 " \
        "{%0,%1,%2,%3}, {%4,%5,%6,%7}, {%8,%9}, {%0,%1,%2,%3};" \
        : "+f"((C)[0]), "+f"((C)[1]), "+f"((C)[2]), "+f"((C)[3]) \
        : "r"((A)[0]), "r"((A)[1]), "r"((A)[2]), "r"((A)[3]), \
          "r"((B)[0]), "r"((B)[1]))

// ---------------- CSR build -------------------------------------------------
__global__ void k_hist(const int4* __restrict__ dst4) {
    int i = blockIdx.x * blockDim.x + threadIdx.x;
    if (i < EE / 4) {
        int4 d = dst4[i];
        atomicAdd(&g_deg[d.x], 1);
        atomicAdd(&g_deg[d.y], 1);
        atomicAdd(&g_deg[d.z], 1);
        atomicAdd(&g_deg[d.w], 1);
    }
}

__global__ __launch_bounds__(1024) void k_scan_part() {
    __shared__ int ws[32];
    const int tid = threadIdx.x, lane = tid & 31, wid = tid >> 5;
    int i = blockIdx.x * 1024 + tid;
    int v = (i < NN) ? g_deg[i] : 0;
    int x = v;
    #pragma unroll
    for (int o = 1; o < 32; o <<= 1) {
        int t = __shfl_up_sync(0xffffffffu, x, o);
        if (lane >= o) x += t;
    }
    if (lane == 31) ws[wid] = x;
    __syncthreads();
    if (wid == 0) {
        int y = ws[lane];
        #pragma unroll
        for (int o = 1; o < 32; o <<= 1) {
            int t = __shfl_up_sync(0xffffffffu, y, o);
            if (lane >= o) y += t;
        }
        ws[lane] = y;
    }
    __syncthreads();
    int excl = x - v + ((wid > 0) ? ws[wid - 1] : 0);
    if (i < NN) g_off[i] = excl;
    if (tid == 1023) g_bsum[blockIdx.x] = excl + v;
}

__global__ __launch_bounds__(1024) void k_scan_apply() {
    __shared__ int s_pre[2];
    const int tid = threadIdx.x, bid = blockIdx.x;
    if (tid < 64) {
        int v = (tid < bid) ? g_bsum[tid] : 0;
        #pragma unroll
        for (int o = 16; o; o >>= 1) v += __shfl_xor_sync(0xffffffffu, v, o);
        if ((tid & 31) == 0) s_pre[tid >> 5] = v;
    }
    __syncthreads();
    int bp = s_pre[0] + s_pre[1];
    int i = bid * 1024 + tid;
    if (i < NN) {
        int o = g_off[i] + bp;
        g_off[i] = o;
        g_cur[i] = o;
        g_deg[i] = 0;    // self-clean
    }
    if (bid == NBLK - 1 && tid == 1023) g_off[NN] = bp + g_bsum[NBLK - 1];
}

// scatter fused with edge-attention-term computation (needs g_ced ready)
__global__ void k_scatter(const int* __restrict__ src, const int* __restrict__ dst,
                          const float* __restrict__ eatt) {
    int e = blockIdx.x * blockDim.x + threadIdx.x;
    if (e >= EE) return;
    const float4* er = (const float4*)(eatt + (size_t)e * 8);
    float4 e0 = er[0], e1 = er[1];
    float ae0 = e0.x * g_ced[0] + e0.y * g_ced[1] + e0.z * g_ced[2] + e0.w * g_ced[3]
              + e1.x * g_ced[4] + e1.y * g_ced[5] + e1.z * g_ced[6] + e1.w * g_ced[7];
    float ae1 = e0.x * g_ced[8] + e0.y * g_ced[9] + e0.z * g_ced[10] + e0.w * g_ced[11]
              + e1.x * g_ced[12] + e1.y * g_ced[13] + e1.z * g_ced[14] + e1.w * g_ced[15];
    int p = atomicAdd(&g_cur[dst[e]], 1);
    g_ssrc[p] = src[e];
    g_aes[p] = make_float2(ae0, ae1);
}

// ---------------- ced for both layers ---------------------------------------
__global__ void k_ced(const float* __restrict__ We0, const float* __restrict__ ae0,
                      const float* __restrict__ We1, const float* __restrict__ ae1) {
    int j = threadIdx.x;
    if (j < 8) {
        float s = 0.f;
        for (int c = 0; c < 128; c++) s += We0[j * 128 + c] * ae0[c];
        g_ced[j] = s;
    } else if (j < 16) {
        int jj = j - 8;
        float s = 0.f;
        for (int c = 0; c < 112; c++) s += We1[jj * 112 + c] * ae1[c];
        g_ced[j] = s;
    }
}

// ---- tf32 tensor-core GEMM (+optional BN-relu pre, +al epilogue) -----------
// Out[N,COUT] = A[N,128] @ W[128,COUT]. Block: 128 rows, 8 warps (4m x 2n).
template <int COUT, bool PRE>
__launch_bounds__(256)
__global__ void k_gemm(const float* __restrict__ A, const float* __restrict__ W,
                       const float* __restrict__ asrc, const float* __restrict__ adst,
                       float* __restrict__ Out) {
    __shared__ float As[128 * 36];   // [row][k], stride 36 (bank-permuting)
    __shared__ float Bs[128 * 36];   // [n][k],   stride 36
    __shared__ float alsm[2][128], aldm[2][128];
    __shared__ float asv[128], adv[128];

    const int tid = threadIdx.x;
    const int lane = tid & 31, w = tid >> 5;
    const int mrow = (w & 3) * 32;       // warp m-offset
    const int nwarp = w >> 2;            // 0 or 1
    const int ncol = nwarp * 64;         // warp n-offset
    const int row0 = blockIdx.x * 128;

    if (tid < 128) {
        asv[tid] = (tid < COUT) ? asrc[tid] : 0.f;
        adv[tid] = (tid < COUT) ? adst[tid] : 0.f;
    }

    float acc[2][8][4];
    #pragma unroll
    for (int mt = 0; mt < 2; mt++)
        #pragma unroll
        for (int nt = 0; nt < 8; nt++)
            #pragma unroll
            for (int j = 0; j < 4; j++) acc[mt][nt][j] = 0.f;

    float4 aReg[4];
    float bReg[16];

    auto loadA = [&](int k0) {
        #pragma unroll
        for (int t = 0; t < 4; t++) {
            int idx = tid + t * 256;
            int r = idx >> 3, c4 = (idx & 7) * 4;
            int gr = row0 + r;
            float4 v = make_float4(0.f, 0.f, 0.f, 0.f);
            if (gr < NN) {
                v = *(const float4*)(A + (size_t)gr * 128 + k0 + c4);
                if (PRE) {
                    int ch = k0 + c4;
                    v.x = fmaxf(fmaf(v.x, g_scale[ch + 0], g_shift[ch + 0]), 0.f);
                    v.y = fmaxf(fmaf(v.y, g_scale[ch + 1], g_shift[ch + 1]), 0.f);
                    v.z = fmaxf(fmaf(v.z, g_scale[ch + 2], g_shift[ch + 2]), 0.f);
                    v.w = fmaxf(fmaf(v.w, g_scale[ch + 3], g_shift[ch + 3]), 0.f);
                }
            }
            aReg[t] = v;
        }
    };
    auto loadB = [&](int k0) {
        #pragma unroll
        for (int t = 0; t < 16; t++) {
            int idx = tid + t * 256;
            int kk = idx >> 7, c = idx & 127;
            bReg[t] = (c < COUT) ? W[(size_t)(k0 + kk) * COUT + c] : 0.f;
        }
    };

    loadA(0);
    loadB(0);

    for (int k0 = 0; k0 < 128; k0 += 32) {
        // commit prefetched chunk to smem (tf32-rounded)
        #pragma unroll
        for (int t = 0; t < 4; t++) {
            int idx = tid + t * 256;
            int r = idx >> 3, c4 = (idx & 7) * 4;
            float* dp = &As[r * 36 + c4];
            dp[0] = f2tf(aReg[t].x); dp[1] = f2tf(aReg[t].y);
            dp[2] = f2tf(aReg[t].z); dp[3] = f2tf(aReg[t].w);
        }
        #pragma unroll
        for (int t = 0; t < 16; t++) {
            int idx = tid + t * 256;
            int kk = idx >> 7, c = idx & 127;
            Bs[c * 36 + kk] = f2tf(bReg[t]);
        }
        __syncthreads();

        if (k0 + 32 < 128) {
            loadA(k0 + 32);
            loadB(k0 + 32);
        }

        #pragma unroll
        for (int ks = 0; ks < 4; ks++) {
            const int kb = ks * 8 + (lane & 3);
            unsigned afr[2][4];
            #pragma unroll
            for (int mt = 0; mt < 2; mt++) {
                int rb = mrow + mt * 16 + (lane >> 2);
                afr[mt][0] = __float_as_uint(As[rb * 36 + kb]);
                afr[mt][1] = __float_as_uint(As[(rb + 8) * 36 + kb]);
                afr[mt][2] = __float_as_uint(As[rb * 36 + kb + 4]);
                afr[mt][3] = __float_as_uint(As[(rb + 8) * 36 + kb + 4]);
            }
            unsigned bfr[8][2];
            #pragma unroll
            for (int nt = 0; nt < 8; nt++) {
                int cb = ncol + nt * 8 + (lane >> 2);
                bfr[nt][0] = __float_as_uint(Bs[cb * 36 + kb]);
                bfr[nt][1] = __float_as_uint(Bs[cb * 36 + kb + 4]);
            }
            #pragma unroll
            for (int mt = 0; mt < 2; mt++)
                #pragma unroll
                for (int nt = 0; nt < 8; nt++)
                    MMA_TF32(acc[mt][nt], afr[mt], bfr[nt]);
        }
        __syncthreads();
    }

    // epilogue: store + attention-logit partials
    float ps[4], pd[4];   // [mt*2 + half]
    #pragma unroll
    for (int j = 0; j < 4; j++) { ps[j] = 0.f; pd[j] = 0.f; }

    #pragma unroll
    for (int mt = 0; mt < 2; mt++) {
        #pragma unroll
        for (int nt = 0; nt < 8; nt++) {
            float* c = acc[mt][nt];
            int r0 = mrow + mt * 16 + (lane >> 2);
            int c0 = ncol + nt * 8 + (lane & 3) * 2;
            int gr0 = row0 + r0, gr1 = gr0 + 8;
            if (c0 < COUT) {
                if (gr0 < NN) {
                    float2 v = make_float2(c[0], c[1]);
                    *(float2*)(Out + (size_t)gr0 * COUT + c0) = v;
                }
                if (gr1 < NN) {
                    float2 v = make_float2(c[2], c[3]);
                    *(float2*)(Out + (size_t)gr1 * COUT + c0) = v;
                }
            }
            float a0 = asv[c0], a1 = asv[c0 + 1];
            float d0 = adv[c0], d1 = adv[c0 + 1];
            ps[mt * 2 + 0] += c[0] * a0 + c[1] * a1;
            ps[mt * 2 + 1] += c[2] * a0 + c[3] * a1;
            pd[mt * 2 + 0] += c[0] * d0 + c[1] * d1;
            pd[mt * 2 + 1] += c[2] * d0 + c[3] * d1;
        }
    }
    // reduce within quad (lanes sharing a row differ in lane&3)
    #pragma unroll
    for (int j = 0; j < 4; j++) {
        ps[j] += __shfl_xor_sync(0xffffffffu, ps[j], 1);
        ps[j] += __shfl_xor_sync(0xffffffffu, ps[j], 2);
        pd[j] += __shfl_xor_sync(0xffffffffu, pd[j], 1);
        pd[j] += __shfl_xor_sync(0xffffffffu, pd[j], 2);
    }
    if ((lane & 3) == 0) {
        #pragma unroll
        for (int mt = 0; mt < 2; mt++) {
            int rb = mrow + mt * 16 + (lane >> 2);
            alsm[nwarp][rb] = ps[mt * 2 + 0];
            alsm[nwarp][rb + 8] = ps[mt * 2 + 1];
            aldm[nwarp][rb] = pd[mt * 2 + 0];
            aldm[nwarp][rb + 8] = pd[mt * 2 + 1];
        }
    }
    __syncthreads();
    if (tid < 128) {
        int gr = row0 + tid;
        if (gr < NN) {
            g_als[gr] = alsm[0][tid] + alsm[1][tid];
            g_ald[gr] = aldm[0][tid] + aldm[1][tid];
        }
    }
}

// ------- warp-per-node single-pass agg (inline logits) + fused BN -----------
template <int C, int AEC>
__launch_bounds__(256)
__global__ void k_agg(const float* __restrict__ bias, float* __restrict__ out,
                      const float* __restrict__ bgam, const float* __restrict__ bbet,
                      int accoff, int scoff, int cidx) {
    __shared__ float s_sum[C];
    __shared__ float s_sq[C];
    __shared__ unsigned s_ticket;
    const int tid = threadIdx.x;
    for (int c = tid; c < C; c += 256) { s_sum[c] = 0.f; s_sq[c] = 0.f; }
    __syncthreads();

    int gw = (blockIdx.x * 256 + tid) >> 5;
    int lane = tid & 31;
    constexpr int NV = C / 4;
    const bool act = lane < NV;

    if (gw < NN) {
        int beg = g_off[gw], end = g_off[gw + 1];
        float aldv = g_ald[gw];

        float den = 0.f;
        float4 acc = make_float4(0.f, 0.f, 0.f, 0.f);
        int p = beg;
        for (; p + 4 <= end; p += 4) {
            int s0 = g_ssrc[p], s1 = g_ssrc[p + 1];
            int s2 = g_ssrc[p + 2], s3 = g_ssrc[p + 3];
            float2 q0 = g_aes[p], q1 = g_aes[p + 1];
            float2 q2 = g_aes[p + 2], q3 = g_aes[p + 3];
            float a0 = g_als[s0] + aldv + (AEC ? q0.y : q0.x);
            float a1 = g_als[s1] + aldv + (AEC ? q1.y : q1.x);
            float a2 = g_als[s2] + aldv + (AEC ? q2.y : q2.x);
            float a3 = g_als[s3] + aldv + (AEC ? q3.y : q3.x);
            a0 = (a0 > 0.f) ? a0 : 0.2f * a0;
            a1 = (a1 > 0.f) ? a1 : 0.2f * a1;
            a2 = (a2 > 0.f) ? a2 : 0.2f * a2;
            a3 = (a3 > 0.f) ? a3 : 0.2f * a3;
            float w0 = __expf(a0), w1 = __expf(a1);
            float w2 = __expf(a2), w3 = __expf(a3);
            den += (w0 + w1) + (w2 + w3);
            if (act) {
                float4 v0 = *(const float4*)(g_xs + (size_t)s0 * C + lane * 4);
                float4 v1 = *(const float4*)(g_xs + (size_t)s1 * C + lane * 4);
                float4 v2 = *(const float4*)(g_xs + (size_t)s2 * C + lane * 4);
                float4 v3 = *(const float4*)(g_xs + (size_t)s3 * C + lane * 4);
                acc.x += (w0 * v0.x + w1 * v1.x) + (w2 * v2.x + w3 * v3.x);
                acc.y += (w0 * v0.y + w1 * v1.y) + (w2 * v2.y + w3 * v3.y);
                acc.z += (w0 * v0.z + w1 * v1.z) + (w2 * v2.z + w3 * v3.z);
                acc.w += (w0 * v0.w + w1 * v1.w) + (w2 * v2.w + w3 * v3.w);
            }
        }
        for (; p < end; p++) {
            int s0 = g_ssrc[p];
            float2 q0 = g_aes[p];
            float a0 = g_als[s0] + aldv + (AEC ? q0.y : q0.x);
            a0 = (a0 > 0.f) ? a0 : 0.2f * a0;
            float w0 = __expf(a0);
            den += w0;
            if (act) {
                float4 v0 = *(const float4*)(g_xs + (size_t)s0 * C + lane * 4);
                acc.x += w0 * v0.x; acc.y += w0 * v0.y;
                acc.z += w0 * v0.z; acc.w += w0 * v0.w;
            }
        }
        float inv = (end > beg) ? 1.f / den : 0.f;
        if (act) {
            float4 b = *(const float4*)(bias + lane * 4);
            acc.x = fmaf(acc.x, inv, b.x);
            acc.y = fmaf(acc.y, inv, b.y);
            acc.z = fmaf(acc.z, inv, b.z);
            acc.w = fmaf(acc.w, inv, b.w);
            *(float4*)(out + (size_t)gw * C + lane * 4) = acc;
            int c = lane * 4;
            atomicAdd(&s_sum[c + 0], acc.x); atomicAdd(&s_sq[c + 0], acc.x * acc.x);
            atomicAdd(&s_sum[c + 1], acc.y); atomicAdd(&s_sq[c + 1], acc.y * acc.y);
            atomicAdd(&s_sum[c + 2], acc.z); atomicAdd(&s_sq[c + 2], acc.z * acc.z);
            atomicAdd(&s_sum[c + 3], acc.w); atomicAdd(&s_sq[c + 3], acc.w * acc.w);
        }
    }
    __syncthreads();
    for (int c = tid; c < C; c += 256) {
        atomicAdd(&g_bnacc[accoff + c], s_sum[c]);
        atomicAdd(&g_bnacc[accoff + 128 + c], s_sq[c]);
    }
    // last-block BN finalize
    __threadfence();
    __syncthreads();
    if (tid == 0) s_ticket = atomicAdd(&g_ctr[cidx], 1u);
    __syncthreads();
    if (s_ticket == gridDim.x - 1) {
        __threadfence();
        if (tid < C) {
            float sum = __ldcg(&g_bnacc[accoff + tid]);
            float sq  = __ldcg(&g_bnacc[accoff + 128 + tid]);
            float mean = sum * (1.f / NN);
            float var = sq * (1.f / NN) - mean * mean;
            float sc = bgam[tid] * rsqrtf(var + 1e-5f);
            g_scale[scoff + tid] = sc;
            g_shift[scoff + tid] = bbet[tid] - mean * sc;
            g_bnacc[accoff + tid] = 0.f;
            g_bnacc[accoff + 128 + tid] = 0.f;
        }
        if (tid == 0) g_ctr[cidx] = 0u;
    }
}

// ---------------- final BN apply ---------------------------------------------
__global__ void k_out(const float* __restrict__ h, float* __restrict__ out) {
    int idx = blockIdx.x * blockDim.x + threadIdx.x;
    int i4 = idx * 4;
    if (i4 < NN * 112) {
        int c = i4 % 112;
        float4 v = *(const float4*)(h + i4);
        v.x = fmaf(v.x, g_scale[128 + c + 0], g_shift[128 + c + 0]);
        v.y = fmaf(v.y, g_scale[128 + c + 1], g_shift[128 + c + 1]);
        v.z = fmaf(v.z, g_scale[128 + c + 2], g_shift[128 + c + 2]);
        v.w = fmaf(v.w, g_scale[128 + c + 3], g_shift[128 + c + 3]);
        *(float4*)(out + i4) = v;
    }
}

// ---------------- launch -----------------------------------------------------
extern "C" void kernel_launch(void* const* d_in, const int* in_sizes, int n_in,
                              void* d_out, int out_size) {
    const float* x    = (const float*)d_in[0];
    const int*   ei   = (const int*)d_in[1];
    const float* eatt = (const float*)d_in[2];
    const float* W0   = (const float*)d_in[3];
    const float* as0  = (const float*)d_in[4];
    const float* ad0  = (const float*)d_in[5];
    const float* We0  = (const float*)d_in[6];
    const float* ae0  = (const float*)d_in[7];
    const float* b0   = (const float*)d_in[8];
    const float* W1   = (const float*)d_in[9];
    const float* as1  = (const float*)d_in[10];
    const float* ad1  = (const float*)d_in[11];
    const float* We1  = (const float*)d_in[12];
    const float* ae1  = (const float*)d_in[13];
    const float* b1   = (const float*)d_in[14];
    const float* bng  = (const float*)d_in[15];
    const float* bnb  = (const float*)d_in[16];
    const float* bfg  = (const float*)d_in[17];
    const float* bfb  = (const float*)d_in[18];
    float* out = (float*)d_out;

    const int* src = ei;
    const int* dst = ei + EE;

    float* p_xs = nullptr;
    float* p_h  = nullptr;
    cudaGetSymbolAddress((void**)&p_xs, g_xs);
    cudaGetSymbolAddress((void**)&p_h,  g_h);

    static cudaStream_t s1 = nullptr;
    static cudaEvent_t evFork = nullptr, evJoin = nullptr;
    if (!s1) {
        cudaStreamCreateWithFlags(&s1, cudaStreamNonBlocking);
        cudaEventCreateWithFlags(&evFork, cudaEventDisableTiming);
        cudaEventCreateWithFlags(&evJoin, cudaEventDisableTiming);
    }

    const int TB = 256;
    const int gE = (EE + TB - 1) / TB;
    const int gE4 = (EE / 4 + TB - 1) / TB;
    const int gW = (NN * 32 + TB - 1) / TB;
    const int gG = (NN + 127) / 128;

    // ---- fork: ced + CSR build (+ae terms inside scatter) on s1, || gemm0
    cudaEventRecord(evFork, 0);
    cudaStreamWaitEvent(s1, evFork, 0);

    k_ced<<<1, 32, 0, s1>>>(We0, ae0, We1, ae1);
    k_hist<<<gE4, TB, 0, s1>>>((const int4*)dst);
    k_scan_part<<<NBLK, 1024, 0, s1>>>();
    k_scan_apply<<<NBLK, 1024, 0, s1>>>();
    k_scatter<<<gE, TB, 0, s1>>>(src, dst, eatt);
    cudaEventRecord(evJoin, s1);

    k_gemm<128, false><<<gG, 256>>>(x, W0, as0, ad0, p_xs);

    cudaStreamWaitEvent(0, evJoin, 0);

    // ---- layer 0 (alpha inline, BN finalize fused)
    k_agg<128, 0><<<gW, TB>>>(b0, p_h, bng, bnb, 0, 0, 0);

    // ---- layer 1 (BN+relu fused into A-load; alpha inline; BN fused)
    k_gemm<112, true><<<gG, 256>>>(p_h, W1, as1, ad1, p_xs);
    k_agg<112, 1><<<gW, TB>>>(b1, p_h, bfg, bfb, 256, 128, 1);
    k_out<<<(NN * 112 / 4 + TB - 1) / TB, TB>>>(p_h, out);
}